// round 2
// baseline (speedup 1.0000x reference)
#include <cuda_runtime.h>
#include <math.h>

// GridPooling: points [B,N,3] f32, features [B,N,F] f32 -> grid [B,32,32,32,F] f32
// B=4, N=100000, F=64, GRID=32 (per reference).
#define GRIDR   32
#define FDIM    64
#define MAXPTS  400000          // B*N upper bound for scratch

__device__ int g_min_bits;
__device__ int g_max_bits;
__device__ int g_gidx[MAXPTS];

// Sign-aware float atomic min/max via integer atomics (works for mixed signs
// given slots are initialized to +/-INF bit patterns).
__device__ __forceinline__ void atomicMinF(int* addr, float v) {
    if (v >= 0.0f) atomicMin(addr, __float_as_int(v));
    else           atomicMax((unsigned int*)addr, __float_as_uint(v));
}
__device__ __forceinline__ void atomicMaxF(int* addr, float v) {
    if (v >= 0.0f) atomicMax(addr, __float_as_int(v));
    else           atomicMin((unsigned int*)addr, __float_as_uint(v));
}

// K0: zero the output grid (harness poisons it) + seed the min/max slots.
__global__ void init_kernel(float4* __restrict__ out, int n4) {
    int i = blockIdx.x * blockDim.x + threadIdx.x;
    if (i < n4) out[i] = make_float4(0.f, 0.f, 0.f, 0.f);
    if (i == 0) {
        g_min_bits = __float_as_int( INFINITY);
        g_max_bits = __float_as_int(-INFINITY);
    }
}

// K1: global min/max over all point coordinates (float4 vectorized).
__global__ void minmax_kernel(const float4* __restrict__ pts, int n4) {
    float lmin =  INFINITY;
    float lmax = -INFINITY;
    int stride = gridDim.x * blockDim.x;
    for (int i = blockIdx.x * blockDim.x + threadIdx.x; i < n4; i += stride) {
        float4 v = pts[i];
        lmin = fminf(lmin, fminf(fminf(v.x, v.y), fminf(v.z, v.w)));
        lmax = fmaxf(lmax, fmaxf(fmaxf(v.x, v.y), fmaxf(v.z, v.w)));
    }
    #pragma unroll
    for (int o = 16; o > 0; o >>= 1) {
        lmin = fminf(lmin, __shfl_xor_sync(0xFFFFFFFFu, lmin, o));
        lmax = fmaxf(lmax, __shfl_xor_sync(0xFFFFFFFFu, lmax, o));
    }
    if ((threadIdx.x & 31) == 0) {
        atomicMinF(&g_min_bits, lmin);
        atomicMaxF(&g_max_bits, lmax);
    }
}

// K2: per-point voxel linear index (matches reference arithmetic exactly:
// normed = (p - pmin) / (pmax - pmin + 1e-6); vox = floor(normed * 32)).
__global__ void gidx_kernel(const float* __restrict__ pts, int np) {
    int p = blockIdx.x * blockDim.x + threadIdx.x;
    if (p >= np) return;
    float pmin  = __int_as_float(g_min_bits);
    float pmax  = __int_as_float(g_max_bits);
    float denom = (pmax - pmin) + 1e-6f;

    float x = pts[p * 3 + 0];
    float y = pts[p * 3 + 1];
    float z = pts[p * 3 + 2];
    int vx = (int)floorf(((x - pmin) / denom) * 32.0f);
    int vy = (int)floorf(((y - pmin) / denom) * 32.0f);
    int vz = (int)floorf(((z - pmin) / denom) * 32.0f);

    int gi;
    if ((unsigned)vx < 32u && (unsigned)vy < 32u && (unsigned)vz < 32u)
        gi = vx * (GRIDR * GRIDR) + vy * GRIDR + vz;
    else
        gi = -1;   // JAX drops OOB scatter indices
    g_gidx[p] = gi;
}

// K3: scatter-max. One thread per (point, 4-feature chunk): coalesced float4
// feature load; atomics only for positive values (zero-init grid => max with 0
// makes non-positive values no-ops; positive floats order as signed ints).
__global__ void scatter_kernel(const float4* __restrict__ feat,
                               float* __restrict__ out,
                               int np, int n_per_batch) {
    int t = blockIdx.x * blockDim.x + threadIdx.x;
    int total = np * (FDIM / 4);
    if (t >= total) return;
    int p = t >> 4;          // point id   (FDIM/4 == 16 chunks per point)
    int c = t & 15;          // chunk id
    int gi = g_gidx[p];
    if (gi < 0) return;
    int b = p / n_per_batch;

    float4 v = feat[t];      // features[p][c*4 .. c*4+3]
    size_t base = ((size_t)(b * (GRIDR * GRIDR * GRIDR) + gi)) * FDIM + (size_t)c * 4;
    int* o = (int*)(out + base);
    if (v.x > 0.0f) atomicMax(o + 0, __float_as_int(v.x));
    if (v.y > 0.0f) atomicMax(o + 1, __float_as_int(v.y));
    if (v.z > 0.0f) atomicMax(o + 2, __float_as_int(v.z));
    if (v.w > 0.0f) atomicMax(o + 3, __float_as_int(v.w));
}

extern "C" void kernel_launch(void* const* d_in, const int* in_sizes, int n_in,
                              void* d_out, int out_size) {
    const float* points   = (const float*)d_in[0];   // B*N*3
    const float* features = (const float*)d_in[1];   // B*N*64

    int np  = in_sizes[0] / 3;          // total points = B*N
    int B   = 4;
    int npb = np / B;                   // points per batch

    // K0: zero output + init min/max slots
    int out4 = out_size / 4;
    {
        int threads = 256;
        int blocks  = (out4 + threads - 1) / threads;
        init_kernel<<<blocks, threads>>>((float4*)d_out, out4);
    }
    // K1: min/max over all coords
    {
        int n4 = in_sizes[0] / 4;       // 1.2M floats -> 300k float4 (divisible)
        int threads = 256;
        int blocks  = 1024;
        minmax_kernel<<<blocks, threads>>>((const float4*)points, n4);
    }
    // K2: voxel indices
    {
        int threads = 256;
        int blocks  = (np + threads - 1) / threads;
        gidx_kernel<<<blocks, threads>>>(points, np);
    }
    // K3: scatter-max
    {
        int total   = np * (FDIM / 4);
        int threads = 256;
        int blocks  = (total + threads - 1) / threads;
        scatter_kernel<<<blocks, threads>>>((const float4*)features,
                                            (float*)d_out, np, npb);
    }
}